// round 15
// baseline (speedup 1.0000x reference)
#include <cuda_runtime.h>
#include <cuda_bf16.h>
#include <cstdint>

// ---------------- problem shapes (fixed) ----------------
#define BSZ   2048
#define NIN   128
#define NHID  512
#define NOUT  128
#define NB    8
#define NF    9
#define K1    (NIN * NF)    // 1152  logical K layer1
#define K2    (NHID * NF)   // 4608  logical K layer2
#define K1E   (3 * K1)      // 3456  logical augmented K (bf16x3)
#define K2E   (3 * K2)      // 13824
#define KP1   (2 * K1)      // 2304  PHYSICAL row length (dedup: [hi|lo])
#define KP2   (2 * K2)      // 9216
#define Z1    6             // split-K slabs layer1 -> KC1 = 576 (9 chunks), grid 384
#define Z2    24            // split-K slabs layer2 -> KC2 = 576 (9 chunks), grid 384
#define KC1   (K1E / Z1)
#define KC2   (K2E / Z2)
#define BKC   64            // K elems per smem chunk (region bounds are multiples)

// Logical K ordering (f-major, GEMM-invariant permutation):
//   k = region*Ktot + f*nIn + i, region in {0,1,2}
// A' logical regions = [hi | lo | hi], B' logical = [hi | hi | lo].
// PHYSICAL storage deduplicated to 2 regions [hi | lo]; GEMM remaps per chunk:
//   kA = (k >= 2*Ktot) ? k - 2*Ktot : k
//   kB = (k >=   Ktot) ? k -   Ktot : k

// ---------------- static device scratch ----------------
__device__ __nv_bfloat16 g_Wt1[(size_t)NHID * KP1];
__device__ __nv_bfloat16 g_Wt2[(size_t)NOUT * KP2];
__device__ __nv_bfloat16 g_F1 [(size_t)BSZ  * KP1];
__device__ __nv_bfloat16 g_F2 [(size_t)BSZ  * KP2];
__device__ float         g_P1 [(size_t)Z1 * BSZ * NHID];
__device__ float         g_P2 [(size_t)Z2 * BSZ * NOUT];
// precomputed knot-difference reciprocals: per row, 30 used (pad 32)
//   R[0..10]  = 1/(t[j+1]-t[j]),  R[11..20] = 1/(t[j+2]-t[j]),  R[21..29] = 1/(t[j+3]-t[j])
__device__ float         g_R1 [NIN  * 32];
__device__ float         g_R2 [NHID * 32];

// ---------------- helpers ----------------
__device__ __forceinline__ uint32_t smem_u32(const void* p) {
    uint32_t a;
    asm("{ .reg .u64 t; cvta.to.shared.u64 t, %1; cvt.u32.u64 %0, t; }" : "=r"(a) : "l"(p));
    return a;
}
__device__ __forceinline__ uint32_t swz(uint32_t off) {   // SW128 swizzle
    return off ^ ((off >> 3) & 0x70);
}
__device__ __forceinline__ void cp_async16(uint32_t saddr, const void* gaddr) {
    asm volatile("cp.async.cg.shared.global [%0], [%1], 16;"
                 :: "r"(saddr), "l"(gaddr) : "memory");
}
__device__ __forceinline__ void cp_commit() {
    asm volatile("cp.async.commit_group;" ::: "memory");
}
template <int N>
__device__ __forceinline__ void cp_wait() {
    asm volatile("cp.async.wait_group %0;" :: "n"(N) : "memory");
}
__device__ __forceinline__ void ldsm_x4(uint32_t& r0, uint32_t& r1, uint32_t& r2,
                                        uint32_t& r3, uint32_t addr) {
    asm volatile("ldmatrix.sync.aligned.m8n8.x4.shared.b16 {%0,%1,%2,%3}, [%4];"
                 : "=r"(r0), "=r"(r1), "=r"(r2), "=r"(r3) : "r"(addr));
}
__device__ __forceinline__ void mma16816(float* d, const uint32_t* a, const uint32_t* b) {
    asm volatile(
        "mma.sync.aligned.m16n8k16.row.col.f32.bf16.bf16.f32 "
        "{%0,%1,%2,%3}, {%4,%5,%6,%7}, {%8,%9}, {%0,%1,%2,%3};"
        : "+f"(d[0]), "+f"(d[1]), "+f"(d[2]), "+f"(d[3])
        : "r"(a[0]), "r"(a[1]), "r"(a[2]), "r"(a[3]), "r"(b[0]), "r"(b[1]));
}

// ---------------------------------------------------------------------------
// Precompute knot-difference reciprocals for both grids (640 rows total).
// Removes ALL fp32 divisions from the expand hot path.
// ---------------------------------------------------------------------------
__global__ void rinv_prep(const float* __restrict__ grid1,
                          const float* __restrict__ grid2,
                          float* __restrict__ R1, float* __restrict__ R2)
{
    int i = blockIdx.x * blockDim.x + threadIdx.x;
    const float* g;
    float* R;
    if (i < NIN)              { g = grid1 + (size_t)i * 12;         R = R1 + i * 32; }
    else if (i < NIN + NHID)  { int j = i - NIN;
                                g = grid2 + (size_t)j * 12;         R = R2 + j * 32; }
    else return;

    float t[12];
    #pragma unroll
    for (int j = 0; j < 12; j++) t[j] = g[j];
    int o = 0;
    #pragma unroll
    for (int p = 1; p <= 3; p++)
        for (int j = 0; j + p < 12; j++)
            R[o++] = 1.0f / (t[j + p] - t[j]);
}

// ---------------------------------------------------------------------------
// Fold weights -> B' [N][2K] physical: hi at k, lo at Ktot+k (k = f*nIn + i).
// ---------------------------------------------------------------------------
__global__ void fold_kernel(const float* __restrict__ coef,
                            const float* __restrict__ sbase,
                            const float* __restrict__ ssp,
                            __nv_bfloat16* __restrict__ Wt,
                            int nIn, int nOut, int Ktot)
{
    int idx = blockIdx.x * blockDim.x + threadIdx.x;
    if (idx >= nIn * nOut) return;
    int o = idx / nIn;
    int i = idx - o * nIn;
    int io = i * nOut + o;
    float sb = sbase[io];
    float sp = ssp[io];
    const float* c = coef + (size_t)io * NB;
    float w[NF];
    w[0] = sb;
    #pragma unroll
    for (int f = 0; f < NB; f++) w[1 + f] = sp * c[f];

    __nv_bfloat16* row = Wt + (size_t)o * (2 * Ktot);
    #pragma unroll
    for (int f = 0; f < NF; f++) {
        float v = w[f];
        __nv_bfloat16 hi = __float2bfloat16(v);
        __nv_bfloat16 lo = __float2bfloat16(v - __bfloat162float(hi));
        int k = f * nIn + i;
        row[k]        = hi;
        row[Ktot + k] = lo;
    }
}

// ---------------------------------------------------------------------------
// Expand (optionally summing split-K slabs of x) -> A' [B][2K] physical:
// hi at k, lo at Ktot+k. Division-free Cox–de Boor via precomputed rinv.
// Two adjacent i per thread -> coalesced bf16x2 stores.
// ---------------------------------------------------------------------------
__global__ void expand_kernel(const float* __restrict__ x, int zsum, int zstride,
                              const float* __restrict__ grid,
                              const float* __restrict__ Rtab,
                              __nv_bfloat16* __restrict__ F,
                              int nIn, int Ktot, int totalPairs)
{
    int p = blockIdx.x * blockDim.x + threadIdx.x;
    if (p >= totalPairs) return;
    const int halfIn = nIn >> 1;
    int b  = p / halfIn;
    int ii = (p - b * halfIn) * 2;

    float xv[2];
    #pragma unroll
    for (int e = 0; e < 2; e++) {
        int gidx = b * nIn + ii + e;
        float v = x[gidx];
        for (int z = 1; z < zsum; z++) v += x[(size_t)z * zstride + gidx];
        xv[e] = v;
    }

    float f9[2][NF];
    #pragma unroll
    for (int e = 0; e < 2; e++) {
        const float* g = grid + (size_t)(ii + e) * 12;
        const float* R = Rtab + (size_t)(ii + e) * 32;
        float t[12];
        #pragma unroll
        for (int j = 0; j < 12; j++) t[j] = g[j];

        float Bv[11];
        #pragma unroll
        for (int j = 0; j < 11; j++)
            Bv[j] = (xv[e] >= t[j] && xv[e] < t[j + 1]) ? 1.0f : 0.0f;

        // q=1 (rinv at offset 0)
        #pragma unroll
        for (int j = 0; j < 10; j++)
            Bv[j] = (xv[e] - t[j]) * R[j] * Bv[j]
                  + (t[j + 2] - xv[e]) * R[j + 1] * Bv[j + 1];
        // q=2 (offset 11)
        #pragma unroll
        for (int j = 0; j < 9; j++)
            Bv[j] = (xv[e] - t[j]) * R[11 + j] * Bv[j]
                  + (t[j + 3] - xv[e]) * R[11 + j + 1] * Bv[j + 1];
        // q=3 (offset 21)
        #pragma unroll
        for (int j = 0; j < 8; j++)
            Bv[j] = (xv[e] - t[j]) * R[21 + j] * Bv[j]
                  + (t[j + 4] - xv[e]) * R[21 + j + 1] * Bv[j + 1];

        f9[e][0] = xv[e] / (1.0f + __expf(-xv[e]));   // silu (1 div + 1 MUFU/elem)
        #pragma unroll
        for (int f = 0; f < NB; f++) f9[e][1 + f] = Bv[f];
    }

    __nv_bfloat16* row = F + (size_t)b * (2 * Ktot);
    #pragma unroll
    for (int f = 0; f < NF; f++) {
        __nv_bfloat16 h0 = __float2bfloat16(f9[0][f]);
        __nv_bfloat16 h1 = __float2bfloat16(f9[1][f]);
        __nv_bfloat162 hi2; hi2.x = h0; hi2.y = h1;
        __nv_bfloat162 lo2;
        lo2.x = __float2bfloat16(f9[0][f] - __bfloat162float(h0));
        lo2.y = __float2bfloat16(f9[1][f] - __bfloat162float(h1));
        int k = f * nIn + ii;
        *reinterpret_cast<__nv_bfloat162*>(&row[k])        = hi2;
        *reinterpret_cast<__nv_bfloat162*>(&row[Ktot + k]) = lo2;
    }
}

// ---------------------------------------------------------------------------
// bf16 GEMM via ldmatrix + mma.sync m16n8k16.
// 128x128 tile, BK=64 double-buffered cp.async, ONE __syncthreads per chunk.
// Logical K span [0, 3*Ktot); physical rows 2*Ktot with per-chunk remap.
// Split-K over blockIdx.z -> fp32 slabs.
// Dynamic smem: 1024 pad + 4 * 16KB = 66560 B.
// ---------------------------------------------------------------------------
__global__ void __launch_bounds__(256)
kan_mma_gemm(const __nv_bfloat16* __restrict__ A,
             const __nv_bfloat16* __restrict__ Bm,
             float* __restrict__ P, int Ntot, int KC, int partStride, int Ktot)
{
    extern __shared__ char dsm[];
    uint32_t tile = (smem_u32(dsm) + 1023u) & ~1023u;
    const uint32_t bufA[2] = { tile,           tile + 32768u };
    const uint32_t bufB[2] = { tile + 16384u,  tile + 49152u };

    const int tid  = threadIdx.x;
    const int lane = tid & 31;
    const int wid  = tid >> 5;
    const int wm   = wid & 1;        // 2 warps along M (64 rows each)
    const int wn   = wid >> 1;       // 4 warps along N (32 cols each)

    const int mrow0 = blockIdx.y * 128;
    const int ncol0 = blockIdx.x * 128;
    const int kbase = blockIdx.z * KC;
    const int nc    = KC >> 6;
    const int ldAB  = 2 * Ktot;      // physical row length (elements)

    // cooperative async tile load: 128 rows x 64 bf16 (128B rows, SW128)
    const int ld_row = tid >> 3;         // 0..31 (x4 iterations -> 128 rows)
    const int ld_ch  = (tid & 7) * 16;   // byte offset within 128B row
    auto issue_tile = [&](const __nv_bfloat16* g, int r0, int k0, uint32_t sb) {
        const char* gb = reinterpret_cast<const char*>(g) + (size_t)k0 * 2 + ld_ch;
        #pragma unroll
        for (int j = 0; j < 4; j++) {
            int row = ld_row + j * 32;
            cp_async16(sb + swz((uint32_t)(row * 128) + ld_ch),
                       gb + (size_t)(r0 + row) * ldAB * 2);
        }
    };
    // logical chunk k -> physical offsets
    auto kA = [&](int k) { return (k >= 2 * Ktot) ? k - 2 * Ktot : k; };
    auto kB = [&](int k) { return (k >= Ktot) ? k - Ktot : k; };

    float acc[4][4][4];
    #pragma unroll
    for (int mt = 0; mt < 4; mt++)
        #pragma unroll
        for (int nt = 0; nt < 4; nt++)
            #pragma unroll
            for (int e = 0; e < 4; e++) acc[mt][nt][e] = 0.0f;

    // per-lane ldmatrix address offsets (within a chunk buffer)
    const uint32_t a_row = (uint32_t)(wm * 64 + (lane & 15));
    const uint32_t a_kb  = (uint32_t)((lane >> 4) * 16);
    const uint32_t b_row = (uint32_t)(wn * 32 + ((lane & 16) >> 1) + (lane & 7));
    const uint32_t b_kb  = (uint32_t)((lane & 8) * 2);

    // prologue
    issue_tile(A,  mrow0, kA(kbase), bufA[0]);
    issue_tile(Bm, ncol0, kB(kbase), bufB[0]);
    cp_commit();

    for (int c = 0; c < nc; c++) {
        const int b = c & 1;
        cp_wait<0>();
        __syncthreads();   // buf b ready for all; all warps done reading buf b^1

        if (c + 1 < nc) {  // loads for c+1 overlap compute of c
            int kn = kbase + (c + 1) * BKC;
            issue_tile(A,  mrow0, kA(kn), bufA[b ^ 1]);
            issue_tile(Bm, ncol0, kB(kn), bufB[b ^ 1]);
            cp_commit();
        }

        const uint32_t cA = bufA[b];
        const uint32_t cB = bufB[b];
        #pragma unroll
        for (int ks = 0; ks < 4; ks++) {
            uint32_t af[4][4], bf[2][4];
            #pragma unroll
            for (int mt = 0; mt < 4; mt++)
                ldsm_x4(af[mt][0], af[mt][1], af[mt][2], af[mt][3],
                        cA + swz((a_row + mt * 16) * 128 + ks * 32 + a_kb));
            #pragma unroll
            for (int nt2 = 0; nt2 < 2; nt2++)
                ldsm_x4(bf[nt2][0], bf[nt2][1], bf[nt2][2], bf[nt2][3],
                        cB + swz((b_row + nt2 * 16) * 128 + ks * 32 + b_kb));
            #pragma unroll
            for (int mt = 0; mt < 4; mt++) {
                #pragma unroll
                for (int nt = 0; nt < 4; nt++)
                    mma16816(acc[mt][nt], af[mt], &bf[nt >> 1][(nt & 1) * 2]);
            }
        }
    }

    // epilogue: direct fp32 stores to split-K slab
    float* Pz = P + (size_t)blockIdx.z * partStride;
    const int er = lane >> 2;          // 0..7
    const int ec = (lane & 3) * 2;     // 0,2,4,6
    #pragma unroll
    for (int mt = 0; mt < 4; mt++) {
        int row = mrow0 + wm * 64 + mt * 16 + er;
        #pragma unroll
        for (int nt = 0; nt < 4; nt++) {
            int col = ncol0 + wn * 32 + nt * 8 + ec;
            float2 v0 = make_float2(acc[mt][nt][0], acc[mt][nt][1]);
            float2 v1 = make_float2(acc[mt][nt][2], acc[mt][nt][3]);
            *reinterpret_cast<float2*>(&Pz[(size_t)row * Ntot + col])       = v0;
            *reinterpret_cast<float2*>(&Pz[(size_t)(row + 8) * Ntot + col]) = v1;
        }
    }
}

// ---------------------------------------------------------------------------
// Deterministic split-K slab reduce (float4-vectorized; n % 4 == 0)
// ---------------------------------------------------------------------------
__global__ void reduce_kernel(const float* __restrict__ P, float* __restrict__ out,
                              int n, int z)
{
    int i4 = blockIdx.x * blockDim.x + threadIdx.x;
    int nq = n >> 2;
    if (i4 >= nq) return;
    float4 s = make_float4(0.f, 0.f, 0.f, 0.f);
    for (int j = 0; j < z; j++) {
        float4 v = *reinterpret_cast<const float4*>(&P[(size_t)j * n + i4 * 4]);
        s.x += v.x; s.y += v.y; s.z += v.z; s.w += v.w;
    }
    *reinterpret_cast<float4*>(&out[i4 * 4]) = s;
}

// ---------------------------------------------------------------------------
extern "C" void kernel_launch(void* const* d_in, const int* in_sizes, int n_in,
                              void* d_out, int out_size)
{
    const float* state = (const float*)d_in[0];
    const float* grid1 = (const float*)d_in[1];
    const float* coef1 = (const float*)d_in[2];
    const float* sb1   = (const float*)d_in[3];
    const float* sp1   = (const float*)d_in[4];
    const float* grid2 = (const float*)d_in[5];
    const float* coef2 = (const float*)d_in[6];
    const float* sb2   = (const float*)d_in[7];
    const float* sp2   = (const float*)d_in[8];
    float* out = (float*)d_out;

    __nv_bfloat16 *Wt1, *Wt2, *F1, *F2;
    float *P1, *P2, *R1, *R2;
    cudaGetSymbolAddress((void**)&Wt1, g_Wt1);
    cudaGetSymbolAddress((void**)&Wt2, g_Wt2);
    cudaGetSymbolAddress((void**)&F1,  g_F1);
    cudaGetSymbolAddress((void**)&F2,  g_F2);
    cudaGetSymbolAddress((void**)&P1,  g_P1);
    cudaGetSymbolAddress((void**)&P2,  g_P2);
    cudaGetSymbolAddress((void**)&R1,  g_R1);
    cudaGetSymbolAddress((void**)&R2,  g_R2);

    const int GEMM_SMEM = 66560;   // 1024 pad + 64KB double-buffered tiles
    cudaFuncSetAttribute(kan_mma_gemm, cudaFuncAttributeMaxDynamicSharedMemorySize,
                         GEMM_SMEM);

    // prep: knot reciprocals (both layers) + folded weights
    rinv_prep<<<(NIN + NHID + 255) / 256, 256>>>(grid1, grid2, R1, R2);
    fold_kernel<<<(NIN * NHID + 255) / 256, 256>>>(coef1, sb1, sp1, Wt1, NIN, NHID, K1);
    fold_kernel<<<(NHID * NOUT + 255) / 256, 256>>>(coef2, sb2, sp2, Wt2, NHID, NOUT, K2);

    // layer 1
    {
        int pairs = BSZ * NIN / 2;
        expand_kernel<<<(pairs + 255) / 256, 256>>>(state, 1, 0, grid1, R1, F1,
                                                    NIN, K1, pairs);
    }
    kan_mma_gemm<<<dim3(NHID / 128, BSZ / 128, Z1), 256, GEMM_SMEM>>>(
        F1, Wt1, P1, NHID, KC1, BSZ * NHID, K1);

    // layer 2 (expand fuses the slab reduction of P1)
    {
        int pairs = BSZ * NHID / 2;
        expand_kernel<<<(pairs + 255) / 256, 256>>>(P1, Z1, BSZ * NHID, grid2, R2, F2,
                                                    NHID, K2, pairs);
    }
    kan_mma_gemm<<<dim3(NOUT / 128, BSZ / 128, Z2), 256, GEMM_SMEM>>>(
        F2, Wt2, P2, NOUT, KC2, BSZ * NOUT, K2);

    reduce_kernel<<<(BSZ * NOUT / 4 + 255) / 256, 256>>>(P2, out, BSZ * NOUT, Z2);
}

// round 16
// speedup vs baseline: 2.3198x; 2.3198x over previous
#include <cuda_runtime.h>
#include <cuda_bf16.h>
#include <cstdint>

// ---------------- problem shapes (fixed) ----------------
#define BSZ   2048
#define NIN   128
#define NHID  512
#define NOUT  128
#define NB    8
#define NF    9
#define K1    (NIN * NF)    // 1152  logical K layer1
#define K2    (NHID * NF)   // 4608  logical K layer2
#define K1E   (3 * K1)      // 3456  logical augmented K (bf16x3)
#define K2E   (3 * K2)      // 13824
#define KP1   (2 * K1)      // 2304  PHYSICAL row length (dedup: [hi|lo])
#define KP2   (2 * K2)      // 9216
#define Z1    6             // split-K slabs layer1 -> KC1 = 576 (9 chunks), grid 384
#define Z2    24            // split-K slabs layer2 -> KC2 = 576 (9 chunks), grid 384
#define KC1   (K1E / Z1)
#define KC2   (K2E / Z2)
#define BKC   64            // K elems per smem chunk (region bounds are multiples)

// Logical K ordering (f-major, GEMM-invariant permutation):
//   k = region*Ktot + f*nIn + i, region in {0,1,2}
// A' logical regions = [hi | lo | hi], B' logical = [hi | hi | lo].
// PHYSICAL storage deduplicated to 2 regions [hi | lo]; GEMM remaps per chunk:
//   kA = (k >= 2*Ktot) ? k - 2*Ktot : k
//   kB = (k >=   Ktot) ? k -   Ktot : k

// ---------------- static device scratch ----------------
__device__ __nv_bfloat16 g_Wt1[(size_t)NHID * KP1];
__device__ __nv_bfloat16 g_Wt2[(size_t)NOUT * KP2];
__device__ __nv_bfloat16 g_F1 [(size_t)BSZ  * KP1];
__device__ __nv_bfloat16 g_F2 [(size_t)BSZ  * KP2];
__device__ float         g_P1 [(size_t)Z1 * BSZ * NHID];
__device__ float         g_P2 [(size_t)Z2 * BSZ * NOUT];
// TRANSPOSED tables (coalesced access: thread pair ii reads float2 at [row*nIn+ii])
//   T_t[j*nIn + i]  : knots, j = 0..11
//   R_t[q*nIn + i]  : knot-difference reciprocals; q 0..10 = level1 (1/(t[j+1]-t[j])),
//                     q 11..20 = level2 (1/(t[j+2]-t[j])), q 21..29 = level3
__device__ float         g_T1t[12 * NIN];
__device__ float         g_R1t[30 * NIN];
__device__ float         g_T2t[12 * NHID];
__device__ float         g_R2t[30 * NHID];

// ---------------- helpers ----------------
__device__ __forceinline__ uint32_t smem_u32(const void* p) {
    uint32_t a;
    asm("{ .reg .u64 t; cvta.to.shared.u64 t, %1; cvt.u32.u64 %0, t; }" : "=r"(a) : "l"(p));
    return a;
}
__device__ __forceinline__ uint32_t swz(uint32_t off) {   // SW128 swizzle
    return off ^ ((off >> 3) & 0x70);
}
__device__ __forceinline__ void cp_async16(uint32_t saddr, const void* gaddr) {
    asm volatile("cp.async.cg.shared.global [%0], [%1], 16;"
                 :: "r"(saddr), "l"(gaddr) : "memory");
}
__device__ __forceinline__ void cp_commit() {
    asm volatile("cp.async.commit_group;" ::: "memory");
}
template <int N>
__device__ __forceinline__ void cp_wait() {
    asm volatile("cp.async.wait_group %0;" :: "n"(N) : "memory");
}
__device__ __forceinline__ void ldsm_x4(uint32_t& r0, uint32_t& r1, uint32_t& r2,
                                        uint32_t& r3, uint32_t addr) {
    asm volatile("ldmatrix.sync.aligned.m8n8.x4.shared.b16 {%0,%1,%2,%3}, [%4];"
                 : "=r"(r0), "=r"(r1), "=r"(r2), "=r"(r3) : "r"(addr));
}
__device__ __forceinline__ void mma16816(float* d, const uint32_t* a, const uint32_t* b) {
    asm volatile(
        "mma.sync.aligned.m16n8k16.row.col.f32.bf16.bf16.f32 "
        "{%0,%1,%2,%3}, {%4,%5,%6,%7}, {%8,%9}, {%0,%1,%2,%3};"
        : "+f"(d[0]), "+f"(d[1]), "+f"(d[2]), "+f"(d[3])
        : "r"(a[0]), "r"(a[1]), "r"(a[2]), "r"(a[3]), "r"(b[0]), "r"(b[1]));
}

// ---------------------------------------------------------------------------
// Precompute TRANSPOSED knot + reciprocal tables (640 rows, trivial cost).
// ---------------------------------------------------------------------------
__global__ void rinv_prep(const float* __restrict__ grid1,
                          const float* __restrict__ grid2,
                          float* __restrict__ T1t, float* __restrict__ R1t,
                          float* __restrict__ T2t, float* __restrict__ R2t)
{
    int idx = blockIdx.x * blockDim.x + threadIdx.x;
    const float* g;
    float *Tt, *Rt;
    int nIn, i;
    if (idx < NIN)             { g = grid1 + (size_t)idx * 12; Tt = T1t; Rt = R1t;
                                 nIn = NIN;  i = idx; }
    else if (idx < NIN + NHID) { i = idx - NIN;
                                 g = grid2 + (size_t)i * 12;  Tt = T2t; Rt = R2t;
                                 nIn = NHID; }
    else return;

    float t[12];
    #pragma unroll
    for (int j = 0; j < 12; j++) t[j] = g[j];
    #pragma unroll
    for (int j = 0; j < 12; j++) Tt[j * nIn + i] = t[j];
    int o = 0;
    #pragma unroll
    for (int p = 1; p <= 3; p++)
        for (int j = 0; j + p < 12; j++) {
            Rt[o * nIn + i] = 1.0f / (t[j + p] - t[j]);
            o++;
        }
}

// ---------------------------------------------------------------------------
// Fold weights -> B' [N][2K] physical: hi at k, lo at Ktot+k (k = f*nIn + i).
// ---------------------------------------------------------------------------
__global__ void fold_kernel(const float* __restrict__ coef,
                            const float* __restrict__ sbase,
                            const float* __restrict__ ssp,
                            __nv_bfloat16* __restrict__ Wt,
                            int nIn, int nOut, int Ktot)
{
    int idx = blockIdx.x * blockDim.x + threadIdx.x;
    if (idx >= nIn * nOut) return;
    int o = idx / nIn;
    int i = idx - o * nIn;
    int io = i * nOut + o;
    float sb = sbase[io];
    float sp = ssp[io];
    const float* c = coef + (size_t)io * NB;
    float w[NF];
    w[0] = sb;
    #pragma unroll
    for (int f = 0; f < NB; f++) w[1 + f] = sp * c[f];

    __nv_bfloat16* row = Wt + (size_t)o * (2 * Ktot);
    #pragma unroll
    for (int f = 0; f < NF; f++) {
        float v = w[f];
        __nv_bfloat16 hi = __float2bfloat16(v);
        __nv_bfloat16 lo = __float2bfloat16(v - __bfloat162float(hi));
        int k = f * nIn + i;
        row[k]        = hi;
        row[Ktot + k] = lo;
    }
}

// ---------------------------------------------------------------------------
// Expand (optionally summing split-K slabs of x) -> A' [B][2K] physical:
// hi at k, lo at Ktot+k. Division-free Cox–de Boor with TRANSPOSED tables:
// every table access is a coalesced float2 (adjacent threads adjacent 8B).
// Two adjacent i per thread -> coalesced bf16x2 stores.
// ---------------------------------------------------------------------------
__global__ void expand_kernel(const float* __restrict__ x, int zsum, int zstride,
                              const float* __restrict__ Tt,
                              const float* __restrict__ Rt,
                              __nv_bfloat16* __restrict__ F,
                              int nIn, int Ktot, int totalPairs)
{
    int p = blockIdx.x * blockDim.x + threadIdx.x;
    if (p >= totalPairs) return;
    const int halfIn = nIn >> 1;
    int b  = p / halfIn;
    int ii = (p - b * halfIn) * 2;

    // input (sum split-K slabs if requested) — float2, fully coalesced
    float2 xv;
    {
        int gidx = b * nIn + ii;
        float2 v = *reinterpret_cast<const float2*>(&x[gidx]);
        for (int z = 1; z < zsum; z++) {
            float2 w = *reinterpret_cast<const float2*>(&x[(size_t)z * zstride + gidx]);
            v.x += w.x; v.y += w.y;
        }
        xv = v;
    }

    // knots (12 coalesced float2 loads)
    float2 t2[12];
    #pragma unroll
    for (int j = 0; j < 12; j++)
        t2[j] = *reinterpret_cast<const float2*>(&Tt[j * nIn + ii]);

    // order-0 indicators
    float2 Bv[11];
    #pragma unroll
    for (int j = 0; j < 11; j++) {
        Bv[j].x = (xv.x >= t2[j].x && xv.x < t2[j + 1].x) ? 1.0f : 0.0f;
        Bv[j].y = (xv.y >= t2[j].y && xv.y < t2[j + 1].y) ? 1.0f : 0.0f;
    }

    // level 1: R rows 0..10
    {
        float2 r[11];
        #pragma unroll
        for (int q = 0; q < 11; q++)
            r[q] = *reinterpret_cast<const float2*>(&Rt[q * nIn + ii]);
        #pragma unroll
        for (int j = 0; j < 10; j++) {
            Bv[j].x = (xv.x - t2[j].x) * r[j].x * Bv[j].x
                    + (t2[j + 2].x - xv.x) * r[j + 1].x * Bv[j + 1].x;
            Bv[j].y = (xv.y - t2[j].y) * r[j].y * Bv[j].y
                    + (t2[j + 2].y - xv.y) * r[j + 1].y * Bv[j + 1].y;
        }
    }
    // level 2: R rows 11..20
    {
        float2 r[10];
        #pragma unroll
        for (int q = 0; q < 10; q++)
            r[q] = *reinterpret_cast<const float2*>(&Rt[(11 + q) * nIn + ii]);
        #pragma unroll
        for (int j = 0; j < 9; j++) {
            Bv[j].x = (xv.x - t2[j].x) * r[j].x * Bv[j].x
                    + (t2[j + 3].x - xv.x) * r[j + 1].x * Bv[j + 1].x;
            Bv[j].y = (xv.y - t2[j].y) * r[j].y * Bv[j].y
                    + (t2[j + 3].y - xv.y) * r[j + 1].y * Bv[j + 1].y;
        }
    }
    // level 3: R rows 21..29
    {
        float2 r[9];
        #pragma unroll
        for (int q = 0; q < 9; q++)
            r[q] = *reinterpret_cast<const float2*>(&Rt[(21 + q) * nIn + ii]);
        #pragma unroll
        for (int j = 0; j < 8; j++) {
            Bv[j].x = (xv.x - t2[j].x) * r[j].x * Bv[j].x
                    + (t2[j + 4].x - xv.x) * r[j + 1].x * Bv[j + 1].x;
            Bv[j].y = (xv.y - t2[j].y) * r[j].y * Bv[j].y
                    + (t2[j + 4].y - xv.y) * r[j + 1].y * Bv[j + 1].y;
        }
    }

    float f9x[NF], f9y[NF];
    f9x[0] = xv.x / (1.0f + __expf(-xv.x));   // silu
    f9y[0] = xv.y / (1.0f + __expf(-xv.y));
    #pragma unroll
    for (int f = 0; f < NB; f++) { f9x[1 + f] = Bv[f].x; f9y[1 + f] = Bv[f].y; }

    __nv_bfloat16* row = F + (size_t)b * (2 * Ktot);
    #pragma unroll
    for (int f = 0; f < NF; f++) {
        __nv_bfloat16 h0 = __float2bfloat16(f9x[f]);
        __nv_bfloat16 h1 = __float2bfloat16(f9y[f]);
        __nv_bfloat162 hi2; hi2.x = h0; hi2.y = h1;
        __nv_bfloat162 lo2;
        lo2.x = __float2bfloat16(f9x[f] - __bfloat162float(h0));
        lo2.y = __float2bfloat16(f9y[f] - __bfloat162float(h1));
        int k = f * nIn + ii;
        *reinterpret_cast<__nv_bfloat162*>(&row[k])        = hi2;
        *reinterpret_cast<__nv_bfloat162*>(&row[Ktot + k]) = lo2;
    }
}

// ---------------------------------------------------------------------------
// bf16 GEMM via ldmatrix + mma.sync m16n8k16.
// 128x128 tile, BK=64 double-buffered cp.async, ONE __syncthreads per chunk.
// Logical K span [0, 3*Ktot); physical rows 2*Ktot with per-chunk remap.
// Split-K over blockIdx.z -> fp32 slabs.
// Dynamic smem: 1024 pad + 4 * 16KB = 66560 B.
// ---------------------------------------------------------------------------
__global__ void __launch_bounds__(256)
kan_mma_gemm(const __nv_bfloat16* __restrict__ A,
             const __nv_bfloat16* __restrict__ Bm,
             float* __restrict__ P, int Ntot, int KC, int partStride, int Ktot)
{
    extern __shared__ char dsm[];
    uint32_t tile = (smem_u32(dsm) + 1023u) & ~1023u;
    const uint32_t bufA[2] = { tile,           tile + 32768u };
    const uint32_t bufB[2] = { tile + 16384u,  tile + 49152u };

    const int tid  = threadIdx.x;
    const int lane = tid & 31;
    const int wid  = tid >> 5;
    const int wm   = wid & 1;        // 2 warps along M (64 rows each)
    const int wn   = wid >> 1;       // 4 warps along N (32 cols each)

    const int mrow0 = blockIdx.y * 128;
    const int ncol0 = blockIdx.x * 128;
    const int kbase = blockIdx.z * KC;
    const int nc    = KC >> 6;
    const int ldAB  = 2 * Ktot;      // physical row length (elements)

    // cooperative async tile load: 128 rows x 64 bf16 (128B rows, SW128)
    const int ld_row = tid >> 3;         // 0..31 (x4 iterations -> 128 rows)
    const int ld_ch  = (tid & 7) * 16;   // byte offset within 128B row
    auto issue_tile = [&](const __nv_bfloat16* g, int r0, int k0, uint32_t sb) {
        const char* gb = reinterpret_cast<const char*>(g) + (size_t)k0 * 2 + ld_ch;
        #pragma unroll
        for (int j = 0; j < 4; j++) {
            int row = ld_row + j * 32;
            cp_async16(sb + swz((uint32_t)(row * 128) + ld_ch),
                       gb + (size_t)(r0 + row) * ldAB * 2);
        }
    };
    // logical chunk k -> physical offsets
    auto kA = [&](int k) { return (k >= 2 * Ktot) ? k - 2 * Ktot : k; };
    auto kB = [&](int k) { return (k >= Ktot) ? k - Ktot : k; };

    float acc[4][4][4];
    #pragma unroll
    for (int mt = 0; mt < 4; mt++)
        #pragma unroll
        for (int nt = 0; nt < 4; nt++)
            #pragma unroll
            for (int e = 0; e < 4; e++) acc[mt][nt][e] = 0.0f;

    // per-lane ldmatrix address offsets (within a chunk buffer)
    const uint32_t a_row = (uint32_t)(wm * 64 + (lane & 15));
    const uint32_t a_kb  = (uint32_t)((lane >> 4) * 16);
    const uint32_t b_row = (uint32_t)(wn * 32 + ((lane & 16) >> 1) + (lane & 7));
    const uint32_t b_kb  = (uint32_t)((lane & 8) * 2);

    // prologue
    issue_tile(A,  mrow0, kA(kbase), bufA[0]);
    issue_tile(Bm, ncol0, kB(kbase), bufB[0]);
    cp_commit();

    for (int c = 0; c < nc; c++) {
        const int b = c & 1;
        cp_wait<0>();
        __syncthreads();   // buf b ready for all; all warps done reading buf b^1

        if (c + 1 < nc) {  // loads for c+1 overlap compute of c
            int kn = kbase + (c + 1) * BKC;
            issue_tile(A,  mrow0, kA(kn), bufA[b ^ 1]);
            issue_tile(Bm, ncol0, kB(kn), bufB[b ^ 1]);
            cp_commit();
        }

        const uint32_t cA = bufA[b];
        const uint32_t cB = bufB[b];
        #pragma unroll
        for (int ks = 0; ks < 4; ks++) {
            uint32_t af[4][4], bf[2][4];
            #pragma unroll
            for (int mt = 0; mt < 4; mt++)
                ldsm_x4(af[mt][0], af[mt][1], af[mt][2], af[mt][3],
                        cA + swz((a_row + mt * 16) * 128 + ks * 32 + a_kb));
            #pragma unroll
            for (int nt2 = 0; nt2 < 2; nt2++)
                ldsm_x4(bf[nt2][0], bf[nt2][1], bf[nt2][2], bf[nt2][3],
                        cB + swz((b_row + nt2 * 16) * 128 + ks * 32 + b_kb));
            #pragma unroll
            for (int mt = 0; mt < 4; mt++) {
                #pragma unroll
                for (int nt = 0; nt < 4; nt++)
                    mma16816(acc[mt][nt], af[mt], &bf[nt >> 1][(nt & 1) * 2]);
            }
        }
    }

    // epilogue: direct fp32 stores to split-K slab
    float* Pz = P + (size_t)blockIdx.z * partStride;
    const int er = lane >> 2;          // 0..7
    const int ec = (lane & 3) * 2;     // 0,2,4,6
    #pragma unroll
    for (int mt = 0; mt < 4; mt++) {
        int row = mrow0 + wm * 64 + mt * 16 + er;
        #pragma unroll
        for (int nt = 0; nt < 4; nt++) {
            int col = ncol0 + wn * 32 + nt * 8 + ec;
            float2 v0 = make_float2(acc[mt][nt][0], acc[mt][nt][1]);
            float2 v1 = make_float2(acc[mt][nt][2], acc[mt][nt][3]);
            *reinterpret_cast<float2*>(&Pz[(size_t)row * Ntot + col])       = v0;
            *reinterpret_cast<float2*>(&Pz[(size_t)(row + 8) * Ntot + col]) = v1;
        }
    }
}

// ---------------------------------------------------------------------------
// Deterministic split-K slab reduce (float4-vectorized; n % 4 == 0)
// ---------------------------------------------------------------------------
__global__ void reduce_kernel(const float* __restrict__ P, float* __restrict__ out,
                              int n, int z)
{
    int i4 = blockIdx.x * blockDim.x + threadIdx.x;
    int nq = n >> 2;
    if (i4 >= nq) return;
    float4 s = make_float4(0.f, 0.f, 0.f, 0.f);
    for (int j = 0; j < z; j++) {
        float4 v = *reinterpret_cast<const float4*>(&P[(size_t)j * n + i4 * 4]);
        s.x += v.x; s.y += v.y; s.z += v.z; s.w += v.w;
    }
    *reinterpret_cast<float4*>(&out[i4 * 4]) = s;
}

// ---------------------------------------------------------------------------
extern "C" void kernel_launch(void* const* d_in, const int* in_sizes, int n_in,
                              void* d_out, int out_size)
{
    const float* state = (const float*)d_in[0];
    const float* grid1 = (const float*)d_in[1];
    const float* coef1 = (const float*)d_in[2];
    const float* sb1   = (const float*)d_in[3];
    const float* sp1   = (const float*)d_in[4];
    const float* grid2 = (const float*)d_in[5];
    const float* coef2 = (const float*)d_in[6];
    const float* sb2   = (const float*)d_in[7];
    const float* sp2   = (const float*)d_in[8];
    float* out = (float*)d_out;

    __nv_bfloat16 *Wt1, *Wt2, *F1, *F2;
    float *P1, *P2, *T1t, *R1t, *T2t, *R2t;
    cudaGetSymbolAddress((void**)&Wt1, g_Wt1);
    cudaGetSymbolAddress((void**)&Wt2, g_Wt2);
    cudaGetSymbolAddress((void**)&F1,  g_F1);
    cudaGetSymbolAddress((void**)&F2,  g_F2);
    cudaGetSymbolAddress((void**)&P1,  g_P1);
    cudaGetSymbolAddress((void**)&P2,  g_P2);
    cudaGetSymbolAddress((void**)&T1t, g_T1t);
    cudaGetSymbolAddress((void**)&R1t, g_R1t);
    cudaGetSymbolAddress((void**)&T2t, g_T2t);
    cudaGetSymbolAddress((void**)&R2t, g_R2t);

    const int GEMM_SMEM = 66560;   // 1024 pad + 64KB double-buffered tiles
    cudaFuncSetAttribute(kan_mma_gemm, cudaFuncAttributeMaxDynamicSharedMemorySize,
                         GEMM_SMEM);

    // prep: transposed knot/reciprocal tables + folded weights
    rinv_prep<<<(NIN + NHID + 255) / 256, 256>>>(grid1, grid2, T1t, R1t, T2t, R2t);
    fold_kernel<<<(NIN * NHID + 255) / 256, 256>>>(coef1, sb1, sp1, Wt1, NIN, NHID, K1);
    fold_kernel<<<(NHID * NOUT + 255) / 256, 256>>>(coef2, sb2, sp2, Wt2, NHID, NOUT, K2);

    // layer 1
    {
        int pairs = BSZ * NIN / 2;
        expand_kernel<<<(pairs + 255) / 256, 256>>>(state, 1, 0, T1t, R1t, F1,
                                                    NIN, K1, pairs);
    }
    kan_mma_gemm<<<dim3(NHID / 128, BSZ / 128, Z1), 256, GEMM_SMEM>>>(
        F1, Wt1, P1, NHID, KC1, BSZ * NHID, K1);

    // layer 2 (expand fuses the slab reduction of P1)
    {
        int pairs = BSZ * NHID / 2;
        expand_kernel<<<(pairs + 255) / 256, 256>>>(P1, Z1, BSZ * NHID, T2t, R2t, F2,
                                                    NHID, K2, pairs);
    }
    kan_mma_gemm<<<dim3(NOUT / 128, BSZ / 128, Z2), 256, GEMM_SMEM>>>(
        F2, Wt2, P2, NOUT, KC2, BSZ * NOUT, K2);

    reduce_kernel<<<(BSZ * NOUT / 4 + 255) / 256, 256>>>(P2, out, BSZ * NOUT, Z2);
}

// round 17
// speedup vs baseline: 2.6696x; 1.1508x over previous
#include <cuda_runtime.h>
#include <cuda_fp16.h>
#include <cstdint>

// ---------------- problem shapes (fixed) ----------------
#define BSZ   2048
#define NIN   128
#define NHID  512
#define NOUT  128
#define NB    8
#define NF    9
#define K1    (NIN * NF)    // 1152  base K layer1
#define K2    (NHID * NF)   // 4608  base K layer2
// fp16 2-term scheme: A' = [a_hi | a_lo] (fp16 split), B' = [b | b] (fp16 once).
// GEMM computes (a_hi + a_lo) * b = a * fp16(b); only error is B's fp16 rounding
// (bound 2^-11 ~ 4.9e-4 << 1e-3 threshold).
#define KL1   (2 * K1)      // 2304  logical augmented K layer1
#define KL2   (2 * K2)      // 9216  logical augmented K layer2
#define Z1    6             // split-K slabs layer1 -> KC1 = 384 (6 chunks), grid 384
#define Z2    24            // split-K slabs layer2 -> KC2 = 384 (6 chunks), grid 384
#define KC1   (KL1 / Z1)
#define KC2   (KL2 / Z2)
#define BKC   64            // K elems per smem chunk (K1,K2 are multiples of 64)

// K ordering within a region (f-major, GEMM-invariant): k = f*nIn + i.
// A physical rows: 2*Ktot ([hi|lo], logical == physical).
// B physical rows: Ktot (single fp16); logical region 1 re-reads region 0:
//   kB = (k >= Ktot) ? k - Ktot : k

// ---------------- static device scratch ----------------
__device__ __half g_Wt1[(size_t)NHID * K1];
__device__ __half g_Wt2[(size_t)NOUT * K2];
__device__ __half g_F1 [(size_t)BSZ  * KL1];
__device__ __half g_F2 [(size_t)BSZ  * KL2];
__device__ float  g_P1 [(size_t)Z1 * BSZ * NHID];
__device__ float  g_P2 [(size_t)Z2 * BSZ * NOUT];
// TRANSPOSED tables (coalesced: thread pair ii reads float2 at [row*nIn+ii])
__device__ float  g_T1t[12 * NIN];
__device__ float  g_R1t[30 * NIN];
__device__ float  g_T2t[12 * NHID];
__device__ float  g_R2t[30 * NHID];

// ---------------- helpers ----------------
__device__ __forceinline__ uint32_t smem_u32(const void* p) {
    uint32_t a;
    asm("{ .reg .u64 t; cvta.to.shared.u64 t, %1; cvt.u32.u64 %0, t; }" : "=r"(a) : "l"(p));
    return a;
}
__device__ __forceinline__ uint32_t swz(uint32_t off) {   // SW128 swizzle
    return off ^ ((off >> 3) & 0x70);
}
__device__ __forceinline__ void cp_async16(uint32_t saddr, const void* gaddr) {
    asm volatile("cp.async.cg.shared.global [%0], [%1], 16;"
                 :: "r"(saddr), "l"(gaddr) : "memory");
}
__device__ __forceinline__ void cp_commit() {
    asm volatile("cp.async.commit_group;" ::: "memory");
}
template <int N>
__device__ __forceinline__ void cp_wait() {
    asm volatile("cp.async.wait_group %0;" :: "n"(N) : "memory");
}
__device__ __forceinline__ void ldsm_x4(uint32_t& r0, uint32_t& r1, uint32_t& r2,
                                        uint32_t& r3, uint32_t addr) {
    asm volatile("ldmatrix.sync.aligned.m8n8.x4.shared.b16 {%0,%1,%2,%3}, [%4];"
                 : "=r"(r0), "=r"(r1), "=r"(r2), "=r"(r3) : "r"(addr));
}
__device__ __forceinline__ void mma16816(float* d, const uint32_t* a, const uint32_t* b) {
    asm volatile(
        "mma.sync.aligned.m16n8k16.row.col.f32.f16.f16.f32 "
        "{%0,%1,%2,%3}, {%4,%5,%6,%7}, {%8,%9}, {%0,%1,%2,%3};"
        : "+f"(d[0]), "+f"(d[1]), "+f"(d[2]), "+f"(d[3])
        : "r"(a[0]), "r"(a[1]), "r"(a[2]), "r"(a[3]), "r"(b[0]), "r"(b[1]));
}

// ---------------------------------------------------------------------------
// Precompute TRANSPOSED knot + reciprocal tables (640 rows, trivial cost).
// ---------------------------------------------------------------------------
__global__ void rinv_prep(const float* __restrict__ grid1,
                          const float* __restrict__ grid2,
                          float* __restrict__ T1t, float* __restrict__ R1t,
                          float* __restrict__ T2t, float* __restrict__ R2t)
{
    int idx = blockIdx.x * blockDim.x + threadIdx.x;
    const float* g;
    float *Tt, *Rt;
    int nIn, i;
    if (idx < NIN)             { g = grid1 + (size_t)idx * 12; Tt = T1t; Rt = R1t;
                                 nIn = NIN;  i = idx; }
    else if (idx < NIN + NHID) { i = idx - NIN;
                                 g = grid2 + (size_t)i * 12;  Tt = T2t; Rt = R2t;
                                 nIn = NHID; }
    else return;

    float t[12];
    #pragma unroll
    for (int j = 0; j < 12; j++) t[j] = g[j];
    #pragma unroll
    for (int j = 0; j < 12; j++) Tt[j * nIn + i] = t[j];
    int o = 0;
    #pragma unroll
    for (int p = 1; p <= 3; p++)
        for (int j = 0; j + p < 12; j++) {
            Rt[o * nIn + i] = 1.0f / (t[j + p] - t[j]);
            o++;
        }
}

// ---------------------------------------------------------------------------
// Fold weights -> B' [N][K] fp16 single region (k = f*nIn + i).
// ---------------------------------------------------------------------------
__global__ void fold_kernel(const float* __restrict__ coef,
                            const float* __restrict__ sbase,
                            const float* __restrict__ ssp,
                            __half* __restrict__ Wt,
                            int nIn, int nOut, int Ktot)
{
    int idx = blockIdx.x * blockDim.x + threadIdx.x;
    if (idx >= nIn * nOut) return;
    int o = idx / nIn;
    int i = idx - o * nIn;
    int io = i * nOut + o;
    float sb = sbase[io];
    float sp = ssp[io];
    const float* c = coef + (size_t)io * NB;
    float w[NF];
    w[0] = sb;
    #pragma unroll
    for (int f = 0; f < NB; f++) w[1 + f] = sp * c[f];

    __half* row = Wt + (size_t)o * Ktot;
    #pragma unroll
    for (int f = 0; f < NF; f++)
        row[f * nIn + i] = __float2half(w[f]);
}

// ---------------------------------------------------------------------------
// Expand (optionally summing split-K slabs of x) -> A' [B][2K] fp16:
// hi at k, lo at Ktot+k. Division-free Cox–de Boor with TRANSPOSED tables
// (all table loads coalesced float2). Two adjacent i per thread -> half2 stores.
// ---------------------------------------------------------------------------
__global__ void expand_kernel(const float* __restrict__ x, int zsum, int zstride,
                              const float* __restrict__ Tt,
                              const float* __restrict__ Rt,
                              __half* __restrict__ F,
                              int nIn, int Ktot, int totalPairs)
{
    int p = blockIdx.x * blockDim.x + threadIdx.x;
    if (p >= totalPairs) return;
    const int halfIn = nIn >> 1;
    int b  = p / halfIn;
    int ii = (p - b * halfIn) * 2;

    // input (sum split-K slabs if requested) — float2, fully coalesced
    float2 xv;
    {
        int gidx = b * nIn + ii;
        float2 v = *reinterpret_cast<const float2*>(&x[gidx]);
        for (int z = 1; z < zsum; z++) {
            float2 w = *reinterpret_cast<const float2*>(&x[(size_t)z * zstride + gidx]);
            v.x += w.x; v.y += w.y;
        }
        xv = v;
    }

    // knots (12 coalesced float2 loads)
    float2 t2[12];
    #pragma unroll
    for (int j = 0; j < 12; j++)
        t2[j] = *reinterpret_cast<const float2*>(&Tt[j * nIn + ii]);

    // order-0 indicators
    float2 Bv[11];
    #pragma unroll
    for (int j = 0; j < 11; j++) {
        Bv[j].x = (xv.x >= t2[j].x && xv.x < t2[j + 1].x) ? 1.0f : 0.0f;
        Bv[j].y = (xv.y >= t2[j].y && xv.y < t2[j + 1].y) ? 1.0f : 0.0f;
    }

    // level 1: R rows 0..10
    {
        float2 r[11];
        #pragma unroll
        for (int q = 0; q < 11; q++)
            r[q] = *reinterpret_cast<const float2*>(&Rt[q * nIn + ii]);
        #pragma unroll
        for (int j = 0; j < 10; j++) {
            Bv[j].x = (xv.x - t2[j].x) * r[j].x * Bv[j].x
                    + (t2[j + 2].x - xv.x) * r[j + 1].x * Bv[j + 1].x;
            Bv[j].y = (xv.y - t2[j].y) * r[j].y * Bv[j].y
                    + (t2[j + 2].y - xv.y) * r[j + 1].y * Bv[j + 1].y;
        }
    }
    // level 2: R rows 11..20
    {
        float2 r[10];
        #pragma unroll
        for (int q = 0; q < 10; q++)
            r[q] = *reinterpret_cast<const float2*>(&Rt[(11 + q) * nIn + ii]);
        #pragma unroll
        for (int j = 0; j < 9; j++) {
            Bv[j].x = (xv.x - t2[j].x) * r[j].x * Bv[j].x
                    + (t2[j + 3].x - xv.x) * r[j + 1].x * Bv[j + 1].x;
            Bv[j].y = (xv.y - t2[j].y) * r[j].y * Bv[j].y
                    + (t2[j + 3].y - xv.y) * r[j + 1].y * Bv[j + 1].y;
        }
    }
    // level 3: R rows 21..29
    {
        float2 r[9];
        #pragma unroll
        for (int q = 0; q < 9; q++)
            r[q] = *reinterpret_cast<const float2*>(&Rt[(21 + q) * nIn + ii]);
        #pragma unroll
        for (int j = 0; j < 8; j++) {
            Bv[j].x = (xv.x - t2[j].x) * r[j].x * Bv[j].x
                    + (t2[j + 4].x - xv.x) * r[j + 1].x * Bv[j + 1].x;
            Bv[j].y = (xv.y - t2[j].y) * r[j].y * Bv[j].y
                    + (t2[j + 4].y - xv.y) * r[j + 1].y * Bv[j + 1].y;
        }
    }

    float f9x[NF], f9y[NF];
    f9x[0] = xv.x / (1.0f + __expf(-xv.x));   // silu
    f9y[0] = xv.y / (1.0f + __expf(-xv.y));
    #pragma unroll
    for (int f = 0; f < NB; f++) { f9x[1 + f] = Bv[f].x; f9y[1 + f] = Bv[f].y; }

    __half* row = F + (size_t)b * (2 * Ktot);
    #pragma unroll
    for (int f = 0; f < NF; f++) {
        __half h0 = __float2half(f9x[f]);
        __half h1 = __float2half(f9y[f]);
        __half2 hi2; hi2.x = h0; hi2.y = h1;
        __half2 lo2;
        lo2.x = __float2half(f9x[f] - __half2float(h0));
        lo2.y = __float2half(f9y[f] - __half2float(h1));
        int k = f * nIn + ii;
        *reinterpret_cast<__half2*>(&row[k])        = hi2;
        *reinterpret_cast<__half2*>(&row[Ktot + k]) = lo2;
    }
}

// ---------------------------------------------------------------------------
// fp16 GEMM via ldmatrix + mma.sync m16n8k16 (f32 accum).
// 128x128 tile, BK=64 double-buffered cp.async, ONE __syncthreads per chunk.
// Logical K span [0, 2*Ktot): A rows are 2*Ktot ([hi|lo], no remap);
// B rows are Ktot, logical region 1 re-reads region 0 (kB fold).
// Split-K over blockIdx.z -> fp32 slabs.
// Dynamic smem: 1024 pad + 4 * 16KB = 66560 B.
// ---------------------------------------------------------------------------
__global__ void __launch_bounds__(256)
kan_mma_gemm(const __half* __restrict__ A,
             const __half* __restrict__ Bm,
             float* __restrict__ P, int Ntot, int KC, int partStride, int Ktot)
{
    extern __shared__ char dsm[];
    uint32_t tile = (smem_u32(dsm) + 1023u) & ~1023u;
    const uint32_t bufA[2] = { tile,           tile + 32768u };
    const uint32_t bufB[2] = { tile + 16384u,  tile + 49152u };

    const int tid  = threadIdx.x;
    const int lane = tid & 31;
    const int wid  = tid >> 5;
    const int wm   = wid & 1;        // 2 warps along M (64 rows each)
    const int wn   = wid >> 1;       // 4 warps along N (32 cols each)

    const int mrow0 = blockIdx.y * 128;
    const int ncol0 = blockIdx.x * 128;
    const int kbase = blockIdx.z * KC;
    const int nc    = KC >> 6;
    const int ldA   = 2 * Ktot;      // A physical row length
    const int ldB   = Ktot;          // B physical row length

    // cooperative async tile load: 128 rows x 64 fp16 (128B rows, SW128)
    const int ld_row = tid >> 3;         // 0..31 (x4 iterations -> 128 rows)
    const int ld_ch  = (tid & 7) * 16;   // byte offset within 128B row
    auto issue_tile = [&](const __half* g, int ld, int r0, int k0, uint32_t sb) {
        const char* gb = reinterpret_cast<const char*>(g) + (size_t)k0 * 2 + ld_ch;
        #pragma unroll
        for (int j = 0; j < 4; j++) {
            int row = ld_row + j * 32;
            cp_async16(sb + swz((uint32_t)(row * 128) + ld_ch),
                       gb + (size_t)(r0 + row) * ld * 2);
        }
    };
    // logical chunk k -> physical B offset (region 1 re-reads region 0)
    auto kB = [&](int k) { return (k >= Ktot) ? k - Ktot : k; };

    float acc[4][4][4];
    #pragma unroll
    for (int mt = 0; mt < 4; mt++)
        #pragma unroll
        for (int nt = 0; nt < 4; nt++)
            #pragma unroll
            for (int e = 0; e < 4; e++) acc[mt][nt][e] = 0.0f;

    // per-lane ldmatrix address offsets (within a chunk buffer)
    const uint32_t a_row = (uint32_t)(wm * 64 + (lane & 15));
    const uint32_t a_kb  = (uint32_t)((lane >> 4) * 16);
    const uint32_t b_row = (uint32_t)(wn * 32 + ((lane & 16) >> 1) + (lane & 7));
    const uint32_t b_kb  = (uint32_t)((lane & 8) * 2);

    // prologue
    issue_tile(A,  ldA, mrow0, kbase, bufA[0]);
    issue_tile(Bm, ldB, ncol0, kB(kbase), bufB[0]);
    cp_commit();

    for (int c = 0; c < nc; c++) {
        const int b = c & 1;
        cp_wait<0>();
        __syncthreads();   // buf b ready for all; all warps done reading buf b^1

        if (c + 1 < nc) {  // loads for c+1 overlap compute of c
            int kn = kbase + (c + 1) * BKC;
            issue_tile(A,  ldA, mrow0, kn, bufA[b ^ 1]);
            issue_tile(Bm, ldB, ncol0, kB(kn), bufB[b ^ 1]);
            cp_commit();
        }

        const uint32_t cA = bufA[b];
        const uint32_t cB = bufB[b];
        #pragma unroll
        for (int ks = 0; ks < 4; ks++) {
            uint32_t af[4][4], bf[2][4];
            #pragma unroll
            for (int mt = 0; mt < 4; mt++)
                ldsm_x4(af[mt][0], af[mt][1], af[mt][2], af[mt][3],
                        cA + swz((a_row + mt * 16) * 128 + ks * 32 + a_kb));
            #pragma unroll
            for (int nt2 = 0; nt2 < 2; nt2++)
                ldsm_x4(bf[nt2][0], bf[nt2][1], bf[nt2][2], bf[nt2][3],
                        cB + swz((b_row + nt2 * 16) * 128 + ks * 32 + b_kb));
            #pragma unroll
            for (int mt = 0; mt < 4; mt++) {
                #pragma unroll
                for (int nt = 0; nt < 4; nt++)
                    mma16816(acc[mt][nt], af[mt], &bf[nt >> 1][(nt & 1) * 2]);
            }
        }
    }

    // epilogue: direct fp32 stores to split-K slab
    float* Pz = P + (size_t)blockIdx.z * partStride;
    const int er = lane >> 2;          // 0..7
    const int ec = (lane & 3) * 2;     // 0,2,4,6
    #pragma unroll
    for (int mt = 0; mt < 4; mt++) {
        int row = mrow0 + wm * 64 + mt * 16 + er;
        #pragma unroll
        for (int nt = 0; nt < 4; nt++) {
            int col = ncol0 + wn * 32 + nt * 8 + ec;
            float2 v0 = make_float2(acc[mt][nt][0], acc[mt][nt][1]);
            float2 v1 = make_float2(acc[mt][nt][2], acc[mt][nt][3]);
            *reinterpret_cast<float2*>(&Pz[(size_t)row * Ntot + col])       = v0;
            *reinterpret_cast<float2*>(&Pz[(size_t)(row + 8) * Ntot + col]) = v1;
        }
    }
}

// ---------------------------------------------------------------------------
// Deterministic split-K slab reduce (float4-vectorized; n % 4 == 0)
// ---------------------------------------------------------------------------
__global__ void reduce_kernel(const float* __restrict__ P, float* __restrict__ out,
                              int n, int z)
{
    int i4 = blockIdx.x * blockDim.x + threadIdx.x;
    int nq = n >> 2;
    if (i4 >= nq) return;
    float4 s = make_float4(0.f, 0.f, 0.f, 0.f);
    for (int j = 0; j < z; j++) {
        float4 v = *reinterpret_cast<const float4*>(&P[(size_t)j * n + i4 * 4]);
        s.x += v.x; s.y += v.y; s.z += v.z; s.w += v.w;
    }
    *reinterpret_cast<float4*>(&out[i4 * 4]) = s;
}

// ---------------------------------------------------------------------------
extern "C" void kernel_launch(void* const* d_in, const int* in_sizes, int n_in,
                              void* d_out, int out_size)
{
    const float* state = (const float*)d_in[0];
    const float* grid1 = (const float*)d_in[1];
    const float* coef1 = (const float*)d_in[2];
    const float* sb1   = (const float*)d_in[3];
    const float* sp1   = (const float*)d_in[4];
    const float* grid2 = (const float*)d_in[5];
    const float* coef2 = (const float*)d_in[6];
    const float* sb2   = (const float*)d_in[7];
    const float* sp2   = (const float*)d_in[8];
    float* out = (float*)d_out;

    __half *Wt1, *Wt2, *F1, *F2;
    float *P1, *P2, *T1t, *R1t, *T2t, *R2t;
    cudaGetSymbolAddress((void**)&Wt1, g_Wt1);
    cudaGetSymbolAddress((void**)&Wt2, g_Wt2);
    cudaGetSymbolAddress((void**)&F1,  g_F1);
    cudaGetSymbolAddress((void**)&F2,  g_F2);
    cudaGetSymbolAddress((void**)&P1,  g_P1);
    cudaGetSymbolAddress((void**)&P2,  g_P2);
    cudaGetSymbolAddress((void**)&T1t, g_T1t);
    cudaGetSymbolAddress((void**)&R1t, g_R1t);
    cudaGetSymbolAddress((void**)&T2t, g_T2t);
    cudaGetSymbolAddress((void**)&R2t, g_R2t);

    const int GEMM_SMEM = 66560;   // 1024 pad + 64KB double-buffered tiles
    cudaFuncSetAttribute(kan_mma_gemm, cudaFuncAttributeMaxDynamicSharedMemorySize,
                         GEMM_SMEM);

    // prep: transposed knot/reciprocal tables + folded weights
    rinv_prep<<<(NIN + NHID + 255) / 256, 256>>>(grid1, grid2, T1t, R1t, T2t, R2t);
    fold_kernel<<<(NIN * NHID + 255) / 256, 256>>>(coef1, sb1, sp1, Wt1, NIN, NHID, K1);
    fold_kernel<<<(NHID * NOUT + 255) / 256, 256>>>(coef2, sb2, sp2, Wt2, NHID, NOUT, K2);

    // layer 1
    {
        int pairs = BSZ * NIN / 2;
        expand_kernel<<<(pairs + 255) / 256, 256>>>(state, 1, 0, T1t, R1t, F1,
                                                    NIN, K1, pairs);
    }
    kan_mma_gemm<<<dim3(NHID / 128, BSZ / 128, Z1), 256, GEMM_SMEM>>>(
        F1, Wt1, P1, NHID, KC1, BSZ * NHID, K1);

    // layer 2 (expand fuses the slab reduction of P1)
    {
        int pairs = BSZ * NHID / 2;
        expand_kernel<<<(pairs + 255) / 256, 256>>>(P1, Z1, BSZ * NHID, T2t, R2t, F2,
                                                    NHID, K2, pairs);
    }
    kan_mma_gemm<<<dim3(NOUT / 128, BSZ / 128, Z2), 256, GEMM_SMEM>>>(
        F2, Wt2, P2, NOUT, KC2, BSZ * NOUT, K2);

    reduce_kernel<<<(BSZ * NOUT / 4 + 255) / 256, 256>>>(P2, out, BSZ * NOUT, Z2);
}